// round 1
// baseline (speedup 1.0000x reference)
#include <cuda_runtime.h>
#include <math.h>

#define BATCH 8192
#define HID   1024

// Scratch (static device globals — no allocation).
__device__ float g_r[BATCH * HID];    // r_pre  -> r_t * hidden
__device__ float g_z[BATCH * HID];    // z_pre  -> sigmoid(z_pre)
__device__ float g_xh[BATCH * HID];   // x @ Wxh^T + bh
__device__ float g_c[BATCH * HID];    // c_pre
__device__ float g_hat[BATCH * HID];  // hat_pre -> a_t * relu(hat_pre)

// MODE 0: C = A@B^T + bias      (beta = 0)
// MODE 1: C += A@B^T            (accumulate)
// MODE 2: fused final epilogue: out = (1-z)*tanh(acc + xh) + z*hidden + hat
template <int MODE>
__global__ __launch_bounds__(256)
void gemm_kernel(const float* __restrict__ A, int lda,
                 const float* __restrict__ B, int ldb,
                 const float* __restrict__ bias,
                 float* __restrict__ C,
                 const float* __restrict__ xh,
                 const float* __restrict__ z,
                 const float* __restrict__ hprev,
                 const float* __restrict__ hat,
                 float* __restrict__ out)
{
    constexpr int BM = 128, BN = 128, BK = 8;
    __shared__ float As[BK][BM];
    __shared__ float Bs[BK][BN];

    const int tid  = threadIdx.x;
    const int bm   = blockIdx.y * BM;
    const int bn   = blockIdx.x * BN;
    const int tr   = (tid >> 4) << 3;   // 0..120 step 8 (row within tile)
    const int tc   = (tid & 15) << 3;   // 0..120 step 8 (col within tile)
    const int lrow = tid >> 1;          // 0..127
    const int lcol = (tid & 1) << 2;    // 0 or 4

    float acc[8][8];
#pragma unroll
    for (int i = 0; i < 8; i++)
#pragma unroll
        for (int j = 0; j < 8; j++) acc[i][j] = 0.0f;

    const float* Aptr = A + (size_t)(bm + lrow) * lda + lcol;
    const float* Bptr = B + (size_t)(bn + lrow) * ldb + lcol;

    for (int k0 = 0; k0 < 1024; k0 += BK) {
        float4 a4 = *(const float4*)(Aptr + k0);
        float4 b4 = *(const float4*)(Bptr + k0);
        As[lcol + 0][lrow] = a4.x;
        As[lcol + 1][lrow] = a4.y;
        As[lcol + 2][lrow] = a4.z;
        As[lcol + 3][lrow] = a4.w;
        Bs[lcol + 0][lrow] = b4.x;
        Bs[lcol + 1][lrow] = b4.y;
        Bs[lcol + 2][lrow] = b4.z;
        Bs[lcol + 3][lrow] = b4.w;
        __syncthreads();

#pragma unroll
        for (int k = 0; k < BK; k++) {
            float4 a0 = *(const float4*)&As[k][tr];
            float4 a1 = *(const float4*)&As[k][tr + 4];
            float4 b0 = *(const float4*)&Bs[k][tc];
            float4 b1 = *(const float4*)&Bs[k][tc + 4];
            float ar[8] = {a0.x, a0.y, a0.z, a0.w, a1.x, a1.y, a1.z, a1.w};
            float br[8] = {b0.x, b0.y, b0.z, b0.w, b1.x, b1.y, b1.z, b1.w};
#pragma unroll
            for (int i = 0; i < 8; i++)
#pragma unroll
                for (int j = 0; j < 8; j++)
                    acc[i][j] = fmaf(ar[i], br[j], acc[i][j]);
        }
        __syncthreads();
    }

#pragma unroll
    for (int i = 0; i < 8; i++) {
        size_t row = (size_t)(bm + tr + i);
        size_t off = row * HID + bn + tc;
#pragma unroll
        for (int j = 0; j < 8; j++) {
            size_t idx = off + j;
            if (MODE == 0) {
                C[idx] = acc[i][j] + bias[bn + tc + j];
            } else if (MODE == 1) {
                C[idx] += acc[i][j];
            } else {
                float v  = acc[i][j] + xh[idx];
                float ht = tanhf(v);
                float zz = z[idx];
                out[idx] = (1.0f - zz) * ht + zz * hprev[idx] + hat[idx];
            }
        }
    }
}

__device__ __forceinline__ float sigmoidf_(float x) {
    return 1.0f / (1.0f + expf(-x));
}

// One block per row: softmax(c_pre) -> hat = a*relu(hat_pre),
// z = sigmoid(z_pre), r = sigmoid(r_pre)*hidden (in place).
__global__ __launch_bounds__(256)
void elementwise_kernel(const float* __restrict__ hidden,
                        float* __restrict__ r, float* __restrict__ z,
                        const float* __restrict__ c, float* __restrict__ hat)
{
    const int row = blockIdx.x;
    const int tid = threadIdx.x;
    const size_t base = (size_t)row * HID;

    __shared__ float sh[8];

    float v[4];
    float mx = -1e30f;
#pragma unroll
    for (int i = 0; i < 4; i++) {
        v[i] = c[base + tid + i * 256];
        mx = fmaxf(mx, v[i]);
    }
#pragma unroll
    for (int o = 16; o > 0; o >>= 1)
        mx = fmaxf(mx, __shfl_xor_sync(0xffffffffu, mx, o));
    if ((tid & 31) == 0) sh[tid >> 5] = mx;
    __syncthreads();
    mx = sh[0];
#pragma unroll
    for (int i = 1; i < 8; i++) mx = fmaxf(mx, sh[i]);
    __syncthreads();

    float s = 0.0f;
#pragma unroll
    for (int i = 0; i < 4; i++) {
        v[i] = expf(v[i] - mx);
        s += v[i];
    }
#pragma unroll
    for (int o = 16; o > 0; o >>= 1)
        s += __shfl_xor_sync(0xffffffffu, s, o);
    if ((tid & 31) == 0) sh[tid >> 5] = s;
    __syncthreads();
    s = 0.0f;
#pragma unroll
    for (int i = 0; i < 8; i++) s += sh[i];
    const float inv = 1.0f / s;

#pragma unroll
    for (int i = 0; i < 4; i++) {
        size_t idx = base + tid + i * 256;
        float a = v[i] * inv;
        hat[idx] = a * fmaxf(hat[idx], 0.0f);
        z[idx]   = sigmoidf_(z[idx]);
        r[idx]   = sigmoidf_(r[idx]) * hidden[idx];
    }
}

extern "C" void kernel_launch(void* const* d_in, const int* in_sizes, int n_in,
                              void* d_out, int out_size)
{
    (void)in_sizes; (void)n_in; (void)out_size;
    const float* x    = (const float*)d_in[0];
    const float* h    = (const float*)d_in[1];
    const float* Wxr  = (const float*)d_in[2];
    const float* Whr  = (const float*)d_in[3];
    const float* br   = (const float*)d_in[4];
    const float* Wxz  = (const float*)d_in[5];
    const float* Whz  = (const float*)d_in[6];
    const float* bz   = (const float*)d_in[7];
    const float* Wxh  = (const float*)d_in[8];
    const float* Whh  = (const float*)d_in[9];
    const float* bh   = (const float*)d_in[10];
    const float* Wc   = (const float*)d_in[11];
    const float* bc   = (const float*)d_in[12];
    const float* What = (const float*)d_in[13];
    const float* bhat = (const float*)d_in[14];
    float* out = (float*)d_out;

    float *pr, *pz, *pxh, *pc, *phat;
    cudaGetSymbolAddress((void**)&pr,   g_r);
    cudaGetSymbolAddress((void**)&pz,   g_z);
    cudaGetSymbolAddress((void**)&pxh,  g_xh);
    cudaGetSymbolAddress((void**)&pc,   g_c);
    cudaGetSymbolAddress((void**)&phat, g_hat);

    dim3 grid(HID / 128, BATCH / 128);
    dim3 block(256);

    // r_pre = x@Wxr^T + br + h@Whr^T
    gemm_kernel<0><<<grid, block>>>(x, 1024, Wxr, 1024, br, pr, nullptr, nullptr, nullptr, nullptr, nullptr);
    gemm_kernel<1><<<grid, block>>>(h, 1024, Whr, 1024, nullptr, pr, nullptr, nullptr, nullptr, nullptr, nullptr);
    // z_pre
    gemm_kernel<0><<<grid, block>>>(x, 1024, Wxz, 1024, bz, pz, nullptr, nullptr, nullptr, nullptr, nullptr);
    gemm_kernel<1><<<grid, block>>>(h, 1024, Whz, 1024, nullptr, pz, nullptr, nullptr, nullptr, nullptr, nullptr);
    // xh_pre = x@Wxh^T + bh
    gemm_kernel<0><<<grid, block>>>(x, 1024, Wxh, 1024, bh, pxh, nullptr, nullptr, nullptr, nullptr, nullptr);
    // c_pre = combined@Wc^T + bc  (Wc is [H, 2048]; x part cols 0:1024, h part 1024:2048)
    gemm_kernel<0><<<grid, block>>>(x, 1024, Wc, 2048, bc, pc, nullptr, nullptr, nullptr, nullptr, nullptr);
    gemm_kernel<1><<<grid, block>>>(h, 1024, Wc + 1024, 2048, nullptr, pc, nullptr, nullptr, nullptr, nullptr, nullptr);
    // hat_pre
    gemm_kernel<0><<<grid, block>>>(x, 1024, What, 2048, bhat, phat, nullptr, nullptr, nullptr, nullptr, nullptr);
    gemm_kernel<1><<<grid, block>>>(h, 1024, What + 1024, 2048, nullptr, phat, nullptr, nullptr, nullptr, nullptr, nullptr);

    // softmax / sigmoids / gating elementwise
    elementwise_kernel<<<BATCH, block>>>(h, pr, pz, pc, phat);

    // final: acc = (r*h)@Whh^T ; out = (1-z)*tanh(acc+xh) + z*h + hat
    gemm_kernel<2><<<grid, block>>>(pr, 1024, Whh, 1024, nullptr, nullptr, pxh, pz, h, phat, out);
}

// round 3
// speedup vs baseline: 3.4413x; 3.4413x over previous
#include <cuda_runtime.h>
#include <cuda_bf16.h>
#include <cstdint>
#include <math.h>

#define BATCH 8192
#define HID   1024
#define M1    1048576

// ---------------- device scratch (no allocations allowed) ----------------
__device__ __nv_bfloat16 g_whi[10 * M1];
__device__ __nv_bfloat16 g_wlo[10 * M1];
__device__ __nv_bfloat16 g_xhi[BATCH * HID];
__device__ __nv_bfloat16 g_xlo[BATCH * HID];
__device__ __nv_bfloat16 g_hhi[BATCH * HID];
__device__ __nv_bfloat16 g_hlo[BATCH * HID];
__device__ __nv_bfloat16 g_rhhi[BATCH * HID];
__device__ __nv_bfloat16 g_rhlo[BATCH * HID];
__device__ float g_z[BATCH * HID];
__device__ float g_xh[BATCH * HID];
__device__ float g_c[BATCH * HID];
__device__ float g_hat[BATCH * HID];

#define OFF_WXR  0
#define OFF_WHR  (1 * M1)
#define OFF_WXZ  (2 * M1)
#define OFF_WHZ  (3 * M1)
#define OFF_WXH  (4 * M1)
#define OFF_WHH  (5 * M1)
#define OFF_WC   (6 * M1)
#define OFF_WHAT (8 * M1)

// ---------------- helpers ----------------
__device__ __forceinline__ uint32_t smem_u32(const void* p) {
    uint32_t a;
    asm("{ .reg .u64 t; cvta.to.shared.u64 t, %1; cvt.u32.u64 %0, t; }" : "=r"(a) : "l"(p));
    return a;
}
__device__ __forceinline__ void cp16(uint32_t s, const void* g) {
    asm volatile("cp.async.cg.shared.global [%0], [%1], 16;" :: "r"(s), "l"(g));
}
__device__ __forceinline__ void ldsm4(uint32_t (&r)[4], uint32_t addr) {
    asm volatile("ldmatrix.sync.aligned.m8n8.x4.shared.b16 {%0,%1,%2,%3}, [%4];"
        : "=r"(r[0]), "=r"(r[1]), "=r"(r[2]), "=r"(r[3]) : "r"(addr));
}
__device__ __forceinline__ void mma_bf16(float (&d)[4], const uint32_t (&a)[4],
                                         uint32_t b0, uint32_t b1) {
    asm volatile("mma.sync.aligned.m16n8k16.row.col.f32.bf16.bf16.f32 "
        "{%0,%1,%2,%3}, {%4,%5,%6,%7}, {%8,%9}, {%0,%1,%2,%3};"
        : "+f"(d[0]), "+f"(d[1]), "+f"(d[2]), "+f"(d[3])
        : "r"(a[0]), "r"(a[1]), "r"(a[2]), "r"(a[3]), "r"(b0), "r"(b1));
}

// ---------------- GEMM config ----------------
// Tile 128x128, K-chunk 64 (bf16 -> 128B rows, SW128 swizzle), 3-stage cp.async.
// 8 warps: 2 (M) x 4 (N); warp tile 64x32.
#define THREADS 256
#define STAGES 3
#define STAGE_BYTES 16384          // one operand tile: 128 rows * 128B
#define SMEM_TOTAL (STAGES * 2 * STAGE_BYTES)

// load one 64-K chunk: A 128 rows from a (lda=1024), B 128 rows from b (ldb).
__device__ __forceinline__ void load_chunk(uint32_t sA, uint32_t sB,
    const __nv_bfloat16* __restrict__ a, const __nv_bfloat16* __restrict__ b,
    int ldb, int m0, int bn, int k0, int tid)
{
#pragma unroll
    for (int it = 0; it < 4; it++) {
        int s = tid + it * 256;
        int r = s >> 3, cc = s & 7;
        uint32_t off = r * 128 + ((cc * 16) ^ ((r & 7) << 4));
        cp16(sA + off, a + (size_t)(m0 + r) * 1024 + k0 + cc * 8);
    }
#pragma unroll
    for (int it = 0; it < 4; it++) {
        int s = tid + it * 256;
        int r = s >> 3, cc = s & 7;
        uint32_t off = r * 128 + ((cc * 16) ^ ((r & 7) << 4));
        cp16(sB + off, b + (size_t)(bn + r) * (size_t)ldb + k0 + cc * 8);
    }
    asm volatile("cp.async.commit_group;" ::: "memory");
}

// FINAL=0: virtual outputs o=0..4 (r,z,xh,c,hat), grid (40, 64): o=bx>>3, bn=(bx&7)*128
// FINAL=1: o=5 (rh @ Whh^T -> fused output),     grid (8, 64)
template <int FINAL>
__global__ __launch_bounds__(THREADS, 2)
void gemm_tc(const float* __restrict__ br, const float* __restrict__ bz,
             const float* __restrict__ bh, const float* __restrict__ bc,
             const float* __restrict__ bhat, const float* __restrict__ hprev,
             float* __restrict__ out)
{
    extern __shared__ char smem[];
    const uint32_t sb = smem_u32(smem);
    const int tid = threadIdx.x;
    const int lane = tid & 31;
    const int wid = tid >> 5;
    const int wm = wid >> 2;      // 0..1
    const int wn = wid & 3;       // 0..3
    const int m0 = blockIdx.y * 128;

    int o, bn;
    if (FINAL) { o = 5; bn = blockIdx.x * 128; }
    else       { o = blockIdx.x >> 3; bn = (blockIdx.x & 7) * 128; }

    // sources per part (x-part, h-part); 3 terms per part: hi*hi, hi*lo, lo*hi
    const __nv_bfloat16 *aHi[2] = {g_xhi, g_hhi};
    const __nv_bfloat16 *aLo[2] = {g_xlo, g_hlo};
    const __nv_bfloat16 *bHi[2] = {0, 0}, *bLo[2] = {0, 0};
    int ldbv = 1024, npairs = 2;
    const float* bias = 0;
    switch (o) {
        case 0: bHi[0] = g_whi + OFF_WXR; bLo[0] = g_wlo + OFF_WXR;
                bHi[1] = g_whi + OFF_WHR; bLo[1] = g_wlo + OFF_WHR; bias = br; break;
        case 1: bHi[0] = g_whi + OFF_WXZ; bLo[0] = g_wlo + OFF_WXZ;
                bHi[1] = g_whi + OFF_WHZ; bLo[1] = g_wlo + OFF_WHZ; bias = bz; break;
        case 2: bHi[0] = g_whi + OFF_WXH; bLo[0] = g_wlo + OFF_WXH; npairs = 1; bias = bh; break;
        case 3: bHi[0] = g_whi + OFF_WC;        bLo[0] = g_wlo + OFF_WC;
                bHi[1] = g_whi + OFF_WC + 1024; bLo[1] = g_wlo + OFF_WC + 1024;
                ldbv = 2048; bias = bc; break;
        case 4: bHi[0] = g_whi + OFF_WHAT;        bLo[0] = g_wlo + OFF_WHAT;
                bHi[1] = g_whi + OFF_WHAT + 1024; bLo[1] = g_wlo + OFF_WHAT + 1024;
                ldbv = 2048; bias = bhat; break;
        default: aHi[0] = g_rhhi; aLo[0] = g_rhlo;
                 bHi[0] = g_whi + OFF_WHH; bLo[0] = g_wlo + OFF_WHH; npairs = 1; break;
    }

    // per-thread ldmatrix offsets (within a stage tile)
    uint32_t aPre[4], axr[4];
#pragma unroll
    for (int mt = 0; mt < 4; mt++) {
        int r = wm * 64 + mt * 16 + (lane & 15);
        aPre[mt] = r * 128;
        axr[mt] = (r & 7) << 4;
    }
    const uint32_t acx = (lane >> 4) << 4;
    uint32_t bPre[2], bxr[2];
#pragma unroll
    for (int nt = 0; nt < 2; nt++) {
        int r = wn * 32 + nt * 16 + (lane & 7) + ((lane >> 4) << 3);
        bPre[nt] = r * 128;
        bxr[nt] = (r & 7) << 4;
    }
    const uint32_t bcx = ((lane >> 3) & 1) << 4;

    float acc[4][4][4];
#pragma unroll
    for (int i = 0; i < 4; i++)
#pragma unroll
        for (int j = 0; j < 4; j++)
#pragma unroll
            for (int k = 0; k < 4; k++) acc[i][j][k] = 0.0f;

    const int total = npairs * 48;

    // chunk -> (A src, B src, k0)
    auto srcA = [&](int c) -> const __nv_bfloat16* {
        int p = c / 48, t = (c % 48) >> 4;
        return (t == 2) ? aLo[p] : aHi[p];
    };
    auto srcB = [&](int c) -> const __nv_bfloat16* {
        int p = c / 48, t = (c % 48) >> 4;
        return (t == 1) ? bLo[p] : bHi[p];
    };

    // prologue: stages 0,1
    load_chunk(sb + 0 * STAGE_BYTES * 2, sb + 0 * STAGE_BYTES * 2 + STAGE_BYTES,
               srcA(0), srcB(0), ldbv, m0, bn, 0 << 6 & 1023 | ((0 & 15) << 6), tid);
    load_chunk(sb + 1 * STAGE_BYTES * 2, sb + 1 * STAGE_BYTES * 2 + STAGE_BYTES,
               srcA(1), srcB(1), ldbv, m0, bn, (1 & 15) << 6, tid);

    for (int ch = 0; ch < total; ch++) {
        if (ch == total - 1) asm volatile("cp.async.wait_group 0;" ::: "memory");
        else                 asm volatile("cp.async.wait_group 1;" ::: "memory");
        __syncthreads();

        int nc = ch + 2;
        if (nc < total) {
            int st = nc % STAGES;
            load_chunk(sb + st * STAGE_BYTES * 2, sb + st * STAGE_BYTES * 2 + STAGE_BYTES,
                       srcA(nc), srcB(nc), ldbv, m0, bn, (nc & 15) << 6, tid);
        }

        const uint32_t sA = sb + (ch % STAGES) * STAGE_BYTES * 2;
        const uint32_t sB = sA + STAGE_BYTES;
#pragma unroll
        for (int ks = 0; ks < 4; ks++) {
            uint32_t A[4][4];
#pragma unroll
            for (int mt = 0; mt < 4; mt++)
                ldsm4(A[mt], sA + aPre[mt] + ((((uint32_t)ks << 5) | acx) ^ axr[mt]));
            uint32_t B[2][4];
#pragma unroll
            for (int nt = 0; nt < 2; nt++)
                ldsm4(B[nt], sB + bPre[nt] + ((((uint32_t)ks << 5) | bcx) ^ bxr[nt]));
#pragma unroll
            for (int mt = 0; mt < 4; mt++)
#pragma unroll
                for (int j = 0; j < 4; j++)
                    mma_bf16(acc[mt][j], A[mt], B[j >> 1][(j & 1) * 2], B[j >> 1][(j & 1) * 2 + 1]);
        }
    }

    // ---------------- fused epilogue ----------------
#pragma unroll
    for (int mt = 0; mt < 4; mt++) {
#pragma unroll
        for (int j = 0; j < 4; j++) {
            const int c0 = bn + wn * 32 + j * 8 + (lane & 3) * 2;
#pragma unroll
            for (int half = 0; half < 2; half++) {
                const int row = m0 + wm * 64 + mt * 16 + (lane >> 2) + half * 8;
                const size_t idx = (size_t)row * HID + c0;
                float v0 = acc[mt][j][half * 2 + 0];
                float v1 = acc[mt][j][half * 2 + 1];
                if (FINAL) {
                    float t0 = tanhf(v0 + g_xh[idx]);
                    float t1 = tanhf(v1 + g_xh[idx + 1]);
                    float z0 = g_z[idx], z1 = g_z[idx + 1];
                    out[idx]     = (1.0f - z0) * t0 + z0 * hprev[idx]     + g_hat[idx];
                    out[idx + 1] = (1.0f - z1) * t1 + z1 * hprev[idx + 1] + g_hat[idx + 1];
                } else if (o == 0) {
                    float s0 = 1.0f / (1.0f + expf(-(v0 + bias[c0])));
                    float s1 = 1.0f / (1.0f + expf(-(v1 + bias[c0 + 1])));
                    float rh0 = s0 * hprev[idx], rh1 = s1 * hprev[idx + 1];
                    __nv_bfloat16 h0 = __float2bfloat16(rh0);
                    __nv_bfloat16 h1 = __float2bfloat16(rh1);
                    __nv_bfloat162 hp; hp.x = h0; hp.y = h1;
                    __nv_bfloat162 lp;
                    lp.x = __float2bfloat16(rh0 - __bfloat162float(h0));
                    lp.y = __float2bfloat16(rh1 - __bfloat162float(h1));
                    *(__nv_bfloat162*)(g_rhhi + idx) = hp;
                    *(__nv_bfloat162*)(g_rhlo + idx) = lp;
                } else if (o == 1) {
                    g_z[idx]     = 1.0f / (1.0f + expf(-(v0 + bias[c0])));
                    g_z[idx + 1] = 1.0f / (1.0f + expf(-(v1 + bias[c0 + 1])));
                } else if (o == 2) {
                    g_xh[idx]     = v0 + bias[c0];
                    g_xh[idx + 1] = v1 + bias[c0 + 1];
                } else if (o == 3) {
                    g_c[idx]     = v0 + bias[c0];
                    g_c[idx + 1] = v1 + bias[c0 + 1];
                } else {
                    g_hat[idx]     = fmaxf(v0 + bias[c0], 0.0f);
                    g_hat[idx + 1] = fmaxf(v1 + bias[c0 + 1], 0.0f);
                }
            }
        }
    }
}

// ---------------- fp32 -> bf16 hi/lo split ----------------
__global__ __launch_bounds__(256)
void conv_kernel(const float4* __restrict__ src,
                 __nv_bfloat162* __restrict__ hi, __nv_bfloat162* __restrict__ lo)
{
    int i = blockIdx.x * 256 + threadIdx.x;
    float4 f = src[i];
    __nv_bfloat16 hx = __float2bfloat16(f.x), hy = __float2bfloat16(f.y);
    __nv_bfloat16 hz = __float2bfloat16(f.z), hw = __float2bfloat16(f.w);
    __nv_bfloat162 h0; h0.x = hx; h0.y = hy;
    __nv_bfloat162 h1; h1.x = hz; h1.y = hw;
    __nv_bfloat162 l0, l1;
    l0.x = __float2bfloat16(f.x - __bfloat162float(hx));
    l0.y = __float2bfloat16(f.y - __bfloat162float(hy));
    l1.x = __float2bfloat16(f.z - __bfloat162float(hz));
    l1.y = __float2bfloat16(f.w - __bfloat162float(hw));
    hi[2 * i] = h0; hi[2 * i + 1] = h1;
    lo[2 * i] = l0; lo[2 * i + 1] = l1;
}

// ---------------- row softmax: g_hat *= softmax(g_c) ----------------
__global__ __launch_bounds__(256)
void softmax_kernel()
{
    const int row = blockIdx.x;
    const int tid = threadIdx.x;
    const size_t base = (size_t)row * HID;
    __shared__ float sh[8];

    float v[4];
    float mx = -1e30f;
#pragma unroll
    for (int i = 0; i < 4; i++) {
        v[i] = g_c[base + tid + i * 256];
        mx = fmaxf(mx, v[i]);
    }
#pragma unroll
    for (int off = 16; off > 0; off >>= 1) mx = fmaxf(mx, __shfl_xor_sync(0xffffffffu, mx, off));
    if ((tid & 31) == 0) sh[tid >> 5] = mx;
    __syncthreads();
    mx = sh[0];
#pragma unroll
    for (int i = 1; i < 8; i++) mx = fmaxf(mx, sh[i]);
    __syncthreads();

    float s = 0.0f;
#pragma unroll
    for (int i = 0; i < 4; i++) { v[i] = expf(v[i] - mx); s += v[i]; }
#pragma unroll
    for (int off = 16; off > 0; off >>= 1) s += __shfl_xor_sync(0xffffffffu, s, off);
    if ((tid & 31) == 0) sh[tid >> 5] = s;
    __syncthreads();
    s = 0.0f;
#pragma unroll
    for (int i = 0; i < 8; i++) s += sh[i];
    const float inv = 1.0f / s;

#pragma unroll
    for (int i = 0; i < 4; i++) {
        size_t idx = base + tid + i * 256;
        g_hat[idx] *= v[i] * inv;
    }
}

extern "C" void kernel_launch(void* const* d_in, const int* in_sizes, int n_in,
                              void* d_out, int out_size)
{
    (void)in_sizes; (void)n_in; (void)out_size;
    const float* x    = (const float*)d_in[0];
    const float* h    = (const float*)d_in[1];
    const float* Wxr  = (const float*)d_in[2];
    const float* Whr  = (const float*)d_in[3];
    const float* br   = (const float*)d_in[4];
    const float* Wxz  = (const float*)d_in[5];
    const float* Whz  = (const float*)d_in[6];
    const float* bz   = (const float*)d_in[7];
    const float* Wxh  = (const float*)d_in[8];
    const float* Whh  = (const float*)d_in[9];
    const float* bh   = (const float*)d_in[10];
    const float* Wc   = (const float*)d_in[11];
    const float* bc   = (const float*)d_in[12];
    const float* What = (const float*)d_in[13];
    const float* bhat = (const float*)d_in[14];
    float* out = (float*)d_out;

    __nv_bfloat16 *whi, *wlo, *xhi, *xlo, *hhi, *hlo;
    cudaGetSymbolAddress((void**)&whi, g_whi);
    cudaGetSymbolAddress((void**)&wlo, g_wlo);
    cudaGetSymbolAddress((void**)&xhi, g_xhi);
    cudaGetSymbolAddress((void**)&xlo, g_xlo);
    cudaGetSymbolAddress((void**)&hhi, g_hhi);
    cudaGetSymbolAddress((void**)&hlo, g_hlo);

    cudaFuncSetAttribute(gemm_tc<0>, cudaFuncAttributeMaxDynamicSharedMemorySize, SMEM_TOTAL);
    cudaFuncSetAttribute(gemm_tc<1>, cudaFuncAttributeMaxDynamicSharedMemorySize, SMEM_TOTAL);

    conv_kernel<<<8192, 256>>>((const float4*)x, (__nv_bfloat162*)xhi, (__nv_bfloat162*)xlo);
    conv_kernel<<<8192, 256>>>((const float4*)h, (__nv_bfloat162*)hhi, (__nv_bfloat162*)hlo);
    conv_kernel<<<1024, 256>>>((const float4*)Wxr, (__nv_bfloat162*)(whi + OFF_WXR), (__nv_bfloat162*)(wlo + OFF_WXR));
    conv_kernel<<<1024, 256>>>((const float4*)Whr, (__nv_bfloat162*)(whi + OFF_WHR), (__nv_bfloat162*)(wlo + OFF_WHR));
    conv_kernel<<<1024, 256>>>((const float4*)Wxz, (__nv_bfloat162*)(whi + OFF_WXZ), (__nv_bfloat162*)(wlo + OFF_WXZ));
    conv_kernel<<<1024, 256>>>((const float4*)Whz, (__nv_bfloat162*)(whi + OFF_WHZ), (__nv_bfloat162*)(wlo + OFF_WHZ));
    conv_kernel<<<1024, 256>>>((const float4*)Wxh, (__nv_bfloat162*)(whi + OFF_WXH), (__nv_bfloat162*)(wlo + OFF_WXH));
    conv_kernel<<<1024, 256>>>((const float4*)Whh, (__nv_bfloat162*)(whi + OFF_WHH), (__nv_bfloat162*)(wlo + OFF_WHH));
    conv_kernel<<<2048, 256>>>((const float4*)Wc,   (__nv_bfloat162*)(whi + OFF_WC),   (__nv_bfloat162*)(wlo + OFF_WC));
    conv_kernel<<<2048, 256>>>((const float4*)What, (__nv_bfloat162*)(whi + OFF_WHAT), (__nv_bfloat162*)(wlo + OFF_WHAT));

    // fused multi-output GEMM: r (->rh hi/lo), z, xh, c, hat
    gemm_tc<0><<<dim3(40, 64), THREADS, SMEM_TOTAL>>>(br, bz, bh, bc, bhat, h, nullptr);

    // g_hat *= softmax(g_c)
    softmax_kernel<<<BATCH, 256>>>();

    // final: out = (1-z)*tanh(rh@Whh^T + xh) + z*h + hat
    gemm_tc<1><<<dim3(8, 64), THREADS, SMEM_TOTAL>>>(br, bz, bh, bc, bhat, h, out);
}

// round 4
// speedup vs baseline: 3.6313x; 1.0552x over previous
#include <cuda_runtime.h>
#include <cuda_bf16.h>
#include <cstdint>
#include <math.h>

#define BATCH 8192
#define HID   1024
#define M1    1048576

// ---------------- device scratch (no allocations allowed) ----------------
__device__ __nv_bfloat16 g_whi[10 * M1];
__device__ __nv_bfloat16 g_wlo[10 * M1];
__device__ __nv_bfloat16 g_xhi[BATCH * HID];
__device__ __nv_bfloat16 g_xlo[BATCH * HID];
__device__ __nv_bfloat16 g_hhi[BATCH * HID];
__device__ __nv_bfloat16 g_hlo[BATCH * HID];
__device__ __nv_bfloat16 g_rhhi[BATCH * HID];
__device__ __nv_bfloat16 g_rhlo[BATCH * HID];
__device__ float g_z[BATCH * HID];
__device__ float g_c[BATCH * HID];
__device__ float g_hat[BATCH * HID];

#define OFF_WXR  0
#define OFF_WHR  (1 * M1)
#define OFF_WXZ  (2 * M1)
#define OFF_WHZ  (3 * M1)
#define OFF_WXH  (4 * M1)
#define OFF_WHH  (5 * M1)
#define OFF_WC   (6 * M1)
#define OFF_WHAT (8 * M1)

// ---------------- helpers ----------------
__device__ __forceinline__ uint32_t smem_u32(const void* p) {
    uint32_t a;
    asm("{ .reg .u64 t; cvta.to.shared.u64 t, %1; cvt.u32.u64 %0, t; }" : "=r"(a) : "l"(p));
    return a;
}
__device__ __forceinline__ void cp16(uint32_t s, const void* g) {
    asm volatile("cp.async.cg.shared.global [%0], [%1], 16;" :: "r"(s), "l"(g));
}
__device__ __forceinline__ void ldsm4(uint32_t (&r)[4], uint32_t addr) {
    asm volatile("ldmatrix.sync.aligned.m8n8.x4.shared.b16 {%0,%1,%2,%3}, [%4];"
        : "=r"(r[0]), "=r"(r[1]), "=r"(r[2]), "=r"(r[3]) : "r"(addr));
}
__device__ __forceinline__ void mma_bf16(float (&d)[4], const uint32_t (&a)[4],
                                         uint32_t b0, uint32_t b1) {
    asm volatile("mma.sync.aligned.m16n8k16.row.col.f32.bf16.bf16.f32 "
        "{%0,%1,%2,%3}, {%4,%5,%6,%7}, {%8,%9}, {%0,%1,%2,%3};"
        : "+f"(d[0]), "+f"(d[1]), "+f"(d[2]), "+f"(d[3])
        : "r"(a[0]), "r"(a[1]), "r"(a[2]), "r"(a[3]), "r"(b0), "r"(b1));
}

// ---------------- GEMM config ----------------
// Tile 128x128. One pipeline stage holds a K=32 chunk of all four operands:
//   A rows: [A_hi 64B | A_lo 64B] = 128B SW128 rows  (16 KB)
//   B rows: [B_hi 64B | B_lo 64B]                    (16 KB)
// 3 MMA passes per stage: Ahi*Bhi, Alo*Bhi, Ahi*Blo.
// 3 stages x 32 KB = 96 KB/CTA, 2 CTA/SM. 8 warps (2M x 4N), warp tile 64x32.
#define THREADS 256
#define STAGE_BYTES 32768
#define SMEM_TOTAL (3 * STAGE_BYTES)

// load one stage: A 128 rows (hi+lo) + B 128 rows (hi+lo), K-chunk 32
__device__ __forceinline__ void load_stage(uint32_t s,
    const __nv_bfloat16* __restrict__ ahi, const __nv_bfloat16* __restrict__ alo, int m0,
    const __nv_bfloat16* __restrict__ bhi, const __nv_bfloat16* __restrict__ blo,
    int ldb, int bn, int k0, int tid)
{
#pragma unroll
    for (int it = 0; it < 4; it++) {
        int i = tid + it * 256;
        int r = i >> 3;
        int half = (i >> 2) & 1;
        int cc = i & 3;
        uint32_t bo = (uint32_t)(r * 128 + half * 64 + cc * 16);
        uint32_t sw = bo ^ ((uint32_t)(r & 7) << 4);
        const __nv_bfloat16* src = half ? alo : ahi;
        cp16(s + sw, src + (size_t)(m0 + r) * 1024 + k0 + cc * 8);
    }
#pragma unroll
    for (int it = 0; it < 4; it++) {
        int i = tid + it * 256;
        int r = i >> 3;
        int half = (i >> 2) & 1;
        int cc = i & 3;
        uint32_t bo = (uint32_t)(r * 128 + half * 64 + cc * 16);
        uint32_t sw = bo ^ ((uint32_t)(r & 7) << 4);
        const __nv_bfloat16* src = half ? blo : bhi;
        cp16(s + 16384 + sw, src + (size_t)(bn + r) * (size_t)ldb + k0 + cc * 8);
    }
    asm volatile("cp.async.commit_group;" ::: "memory");
}

// FINAL=0: o=0..3 (r,z,c,hat), grid (32, 64): o=bx>>3, bn=(bx&7)*128, npairs=2
// FINAL=1: pairs {rh@Whh^T, x@Wxh^T} accumulated -> fused output, grid (8, 64)
template <int FINAL>
__global__ __launch_bounds__(THREADS, 2)
void gemm_tc(const float* __restrict__ br, const float* __restrict__ bz,
             const float* __restrict__ bh, const float* __restrict__ bc,
             const float* __restrict__ bhat, const float* __restrict__ hprev,
             float* __restrict__ out)
{
    extern __shared__ char smem[];
    const uint32_t sb = smem_u32(smem);
    const int tid = threadIdx.x;
    const int lane = tid & 31;
    const int wid = tid >> 5;
    const int wm = wid >> 2;      // 0..1
    const int wn = wid & 3;       // 0..3
    const int m0 = blockIdx.y * 128;

    int o, bn;
    if (FINAL) { o = 4; bn = blockIdx.x * 128; }
    else       { o = blockIdx.x >> 3; bn = (blockIdx.x & 7) * 128; }

    const __nv_bfloat16 *aHi[2] = {g_xhi, g_hhi};
    const __nv_bfloat16 *aLo[2] = {g_xlo, g_hlo};
    const __nv_bfloat16 *bHi[2] = {0, 0}, *bLo[2] = {0, 0};
    int ldbv = 1024;
    const float* bias = 0;
    switch (o) {
        case 0: bHi[0] = g_whi + OFF_WXR; bLo[0] = g_wlo + OFF_WXR;
                bHi[1] = g_whi + OFF_WHR; bLo[1] = g_wlo + OFF_WHR; bias = br; break;
        case 1: bHi[0] = g_whi + OFF_WXZ; bLo[0] = g_wlo + OFF_WXZ;
                bHi[1] = g_whi + OFF_WHZ; bLo[1] = g_wlo + OFF_WHZ; bias = bz; break;
        case 2: bHi[0] = g_whi + OFF_WC;        bLo[0] = g_wlo + OFF_WC;
                bHi[1] = g_whi + OFF_WC + 1024; bLo[1] = g_wlo + OFF_WC + 1024;
                ldbv = 2048; bias = bc; break;
        case 3: bHi[0] = g_whi + OFF_WHAT;        bLo[0] = g_wlo + OFF_WHAT;
                bHi[1] = g_whi + OFF_WHAT + 1024; bLo[1] = g_wlo + OFF_WHAT + 1024;
                ldbv = 2048; bias = bhat; break;
        default: // FINAL: pair0 = rh@Whh, pair1 = x@Wxh
                 aHi[0] = g_rhhi; aLo[0] = g_rhlo;
                 aHi[1] = g_xhi;  aLo[1] = g_xlo;
                 bHi[0] = g_whi + OFF_WHH; bLo[0] = g_wlo + OFF_WHH;
                 bHi[1] = g_whi + OFF_WXH; bLo[1] = g_wlo + OFF_WXH;
                 bias = bh; break;
    }

    // per-thread ldmatrix row offsets (within a stage tile)
    uint32_t aPre[4], axr[4];
#pragma unroll
    for (int mt = 0; mt < 4; mt++) {
        int r = wm * 64 + mt * 16 + (lane & 15);
        aPre[mt] = (uint32_t)(r * 128);
        axr[mt] = (uint32_t)((r & 7) << 4);
    }
    const uint32_t acx = (uint32_t)(lane >> 4);         // 16B slot offset within k-step
    uint32_t bPre[2], bxr[2];
#pragma unroll
    for (int nt = 0; nt < 2; nt++) {
        int r = wn * 32 + nt * 16 + (lane & 7) + ((lane >> 4) << 3);
        bPre[nt] = (uint32_t)(r * 128);
        bxr[nt] = (uint32_t)((r & 7) << 4);
    }
    const uint32_t bcx = (uint32_t)((lane >> 3) & 1);

    float acc[4][4][4];
#pragma unroll
    for (int i = 0; i < 4; i++)
#pragma unroll
        for (int j = 0; j < 4; j++)
#pragma unroll
            for (int k = 0; k < 4; k++) acc[i][j][k] = 0.0f;

    const int total = 64;   // 2 pairs x 32 K-chunks

    // prologue: stages for chunks 0,1
    load_stage(sb + 0 * STAGE_BYTES, aHi[0], aLo[0], m0, bHi[0], bLo[0], ldbv, bn, 0, tid);
    load_stage(sb + 1 * STAGE_BYTES, aHi[0], aLo[0], m0, bHi[0], bLo[0], ldbv, bn, 32, tid);

    for (int ch = 0; ch < total; ch++) {
        if (ch == total - 1) asm volatile("cp.async.wait_group 0;" ::: "memory");
        else                 asm volatile("cp.async.wait_group 1;" ::: "memory");
        __syncthreads();

        int nc = ch + 2;
        if (nc < total) {
            int p = nc >> 5;
            int st = nc % 3;
            load_stage(sb + st * STAGE_BYTES, aHi[p], aLo[p], m0,
                       bHi[p], bLo[p], ldbv, bn, (nc & 31) * 32, tid);
        }

        const uint32_t sA = sb + (ch % 3) * STAGE_BYTES;
        const uint32_t sB = sA + 16384;
#pragma unroll
        for (int ks = 0; ks < 2; ks++) {
            // slot layout per 128B row: [hi: slots 0..3 | lo: slots 4..7],
            // k-step ks uses 2 slots: ks*2 + {0,1}
            uint32_t Ahi[4][4], Alo[4][4], B[2][4];
            const uint32_t aslotH = (uint32_t)(ks * 2) + acx;
            const uint32_t aslotL = aslotH + 4;
            const uint32_t bslotH = (uint32_t)(ks * 2) + bcx;
            const uint32_t bslotL = bslotH + 4;
#pragma unroll
            for (int mt = 0; mt < 4; mt++)
                ldsm4(Ahi[mt], sA + aPre[mt] + ((aslotH << 4) ^ axr[mt]));
#pragma unroll
            for (int nt = 0; nt < 2; nt++)
                ldsm4(B[nt], sB + bPre[nt] + ((bslotH << 4) ^ bxr[nt]));
            // term0: Ahi * Bhi
#pragma unroll
            for (int mt = 0; mt < 4; mt++)
#pragma unroll
                for (int j = 0; j < 4; j++)
                    mma_bf16(acc[mt][j], Ahi[mt], B[j >> 1][(j & 1) * 2], B[j >> 1][(j & 1) * 2 + 1]);
#pragma unroll
            for (int mt = 0; mt < 4; mt++)
                ldsm4(Alo[mt], sA + aPre[mt] + ((aslotL << 4) ^ axr[mt]));
            // term2: Alo * Bhi
#pragma unroll
            for (int mt = 0; mt < 4; mt++)
#pragma unroll
                for (int j = 0; j < 4; j++)
                    mma_bf16(acc[mt][j], Alo[mt], B[j >> 1][(j & 1) * 2], B[j >> 1][(j & 1) * 2 + 1]);
#pragma unroll
            for (int nt = 0; nt < 2; nt++)
                ldsm4(B[nt], sB + bPre[nt] + ((bslotL << 4) ^ bxr[nt]));
            // term1: Ahi * Blo
#pragma unroll
            for (int mt = 0; mt < 4; mt++)
#pragma unroll
                for (int j = 0; j < 4; j++)
                    mma_bf16(acc[mt][j], Ahi[mt], B[j >> 1][(j & 1) * 2], B[j >> 1][(j & 1) * 2 + 1]);
        }
    }

    // ---------------- fused epilogue ----------------
#pragma unroll
    for (int mt = 0; mt < 4; mt++) {
#pragma unroll
        for (int j = 0; j < 4; j++) {
            const int c0 = bn + wn * 32 + j * 8 + (lane & 3) * 2;
#pragma unroll
            for (int half = 0; half < 2; half++) {
                const int row = m0 + wm * 64 + mt * 16 + (lane >> 2) + half * 8;
                const size_t idx = (size_t)row * HID + c0;
                float v0 = acc[mt][j][half * 2 + 0];
                float v1 = acc[mt][j][half * 2 + 1];
                if (FINAL) {
                    float t0 = tanhf(v0 + bias[c0]);
                    float t1 = tanhf(v1 + bias[c0 + 1]);
                    float z0 = g_z[idx], z1 = g_z[idx + 1];
                    out[idx]     = (1.0f - z0) * t0 + z0 * hprev[idx]     + g_hat[idx];
                    out[idx + 1] = (1.0f - z1) * t1 + z1 * hprev[idx + 1] + g_hat[idx + 1];
                } else if (o == 0) {
                    float s0 = 1.0f / (1.0f + expf(-(v0 + bias[c0])));
                    float s1 = 1.0f / (1.0f + expf(-(v1 + bias[c0 + 1])));
                    float rh0 = s0 * hprev[idx], rh1 = s1 * hprev[idx + 1];
                    __nv_bfloat16 h0 = __float2bfloat16(rh0);
                    __nv_bfloat16 h1 = __float2bfloat16(rh1);
                    __nv_bfloat162 hp; hp.x = h0; hp.y = h1;
                    __nv_bfloat162 lp;
                    lp.x = __float2bfloat16(rh0 - __bfloat162float(h0));
                    lp.y = __float2bfloat16(rh1 - __bfloat162float(h1));
                    *(__nv_bfloat162*)(g_rhhi + idx) = hp;
                    *(__nv_bfloat162*)(g_rhlo + idx) = lp;
                } else if (o == 1) {
                    g_z[idx]     = 1.0f / (1.0f + expf(-(v0 + bias[c0])));
                    g_z[idx + 1] = 1.0f / (1.0f + expf(-(v1 + bias[c0 + 1])));
                } else if (o == 2) {
                    g_c[idx]     = v0 + bias[c0];
                    g_c[idx + 1] = v1 + bias[c0 + 1];
                } else {
                    g_hat[idx]     = fmaxf(v0 + bias[c0], 0.0f);
                    g_hat[idx + 1] = fmaxf(v1 + bias[c0 + 1], 0.0f);
                }
            }
        }
    }
}

// ---------------- fp32 -> bf16 hi/lo split ----------------
__global__ __launch_bounds__(256)
void conv_kernel(const float4* __restrict__ src,
                 __nv_bfloat162* __restrict__ hi, __nv_bfloat162* __restrict__ lo)
{
    int i = blockIdx.x * 256 + threadIdx.x;
    float4 f = src[i];
    __nv_bfloat16 hx = __float2bfloat16(f.x), hy = __float2bfloat16(f.y);
    __nv_bfloat16 hz = __float2bfloat16(f.z), hw = __float2bfloat16(f.w);
    __nv_bfloat162 h0; h0.x = hx; h0.y = hy;
    __nv_bfloat162 h1; h1.x = hz; h1.y = hw;
    __nv_bfloat162 l0, l1;
    l0.x = __float2bfloat16(f.x - __bfloat162float(hx));
    l0.y = __float2bfloat16(f.y - __bfloat162float(hy));
    l1.x = __float2bfloat16(f.z - __bfloat162float(hz));
    l1.y = __float2bfloat16(f.w - __bfloat162float(hw));
    hi[2 * i] = h0; hi[2 * i + 1] = h1;
    lo[2 * i] = l0; lo[2 * i + 1] = l1;
}

// ---------------- row softmax: g_hat *= softmax(g_c) ----------------
__global__ __launch_bounds__(256)
void softmax_kernel()
{
    const int row = blockIdx.x;
    const int tid = threadIdx.x;
    const size_t base = (size_t)row * HID;
    __shared__ float sh[8];

    float v[4];
    float mx = -1e30f;
#pragma unroll
    for (int i = 0; i < 4; i++) {
        v[i] = g_c[base + tid + i * 256];
        mx = fmaxf(mx, v[i]);
    }
#pragma unroll
    for (int off = 16; off > 0; off >>= 1) mx = fmaxf(mx, __shfl_xor_sync(0xffffffffu, mx, off));
    if ((tid & 31) == 0) sh[tid >> 5] = mx;
    __syncthreads();
    mx = sh[0];
#pragma unroll
    for (int i = 1; i < 8; i++) mx = fmaxf(mx, sh[i]);
    __syncthreads();

    float s = 0.0f;
#pragma unroll
    for (int i = 0; i < 4; i++) { v[i] = expf(v[i] - mx); s += v[i]; }
#pragma unroll
    for (int off = 16; off > 0; off >>= 1) s += __shfl_xor_sync(0xffffffffu, s, off);
    if ((tid & 31) == 0) sh[tid >> 5] = s;
    __syncthreads();
    s = 0.0f;
#pragma unroll
    for (int i = 0; i < 8; i++) s += sh[i];
    const float inv = 1.0f / s;

#pragma unroll
    for (int i = 0; i < 4; i++) {
        size_t idx = base + tid + i * 256;
        g_hat[idx] *= v[i] * inv;
    }
}

extern "C" void kernel_launch(void* const* d_in, const int* in_sizes, int n_in,
                              void* d_out, int out_size)
{
    (void)in_sizes; (void)n_in; (void)out_size;
    const float* x    = (const float*)d_in[0];
    const float* h    = (const float*)d_in[1];
    const float* Wxr  = (const float*)d_in[2];
    const float* Whr  = (const float*)d_in[3];
    const float* br   = (const float*)d_in[4];
    const float* Wxz  = (const float*)d_in[5];
    const float* Whz  = (const float*)d_in[6];
    const float* bz   = (const float*)d_in[7];
    const float* Wxh  = (const float*)d_in[8];
    const float* Whh  = (const float*)d_in[9];
    const float* bh   = (const float*)d_in[10];
    const float* Wc   = (const float*)d_in[11];
    const float* bc   = (const float*)d_in[12];
    const float* What = (const float*)d_in[13];
    const float* bhat = (const float*)d_in[14];
    float* out = (float*)d_out;

    __nv_bfloat16 *whi, *wlo, *xhi, *xlo, *hhi, *hlo;
    cudaGetSymbolAddress((void**)&whi, g_whi);
    cudaGetSymbolAddress((void**)&wlo, g_wlo);
    cudaGetSymbolAddress((void**)&xhi, g_xhi);
    cudaGetSymbolAddress((void**)&xlo, g_xlo);
    cudaGetSymbolAddress((void**)&hhi, g_hhi);
    cudaGetSymbolAddress((void**)&hlo, g_hlo);

    cudaFuncSetAttribute(gemm_tc<0>, cudaFuncAttributeMaxDynamicSharedMemorySize, SMEM_TOTAL);
    cudaFuncSetAttribute(gemm_tc<1>, cudaFuncAttributeMaxDynamicSharedMemorySize, SMEM_TOTAL);

    conv_kernel<<<8192, 256>>>((const float4*)x, (__nv_bfloat162*)xhi, (__nv_bfloat162*)xlo);
    conv_kernel<<<8192, 256>>>((const float4*)h, (__nv_bfloat162*)hhi, (__nv_bfloat162*)hlo);
    conv_kernel<<<1024, 256>>>((const float4*)Wxr, (__nv_bfloat162*)(whi + OFF_WXR), (__nv_bfloat162*)(wlo + OFF_WXR));
    conv_kernel<<<1024, 256>>>((const float4*)Whr, (__nv_bfloat162*)(whi + OFF_WHR), (__nv_bfloat162*)(wlo + OFF_WHR));
    conv_kernel<<<1024, 256>>>((const float4*)Wxz, (__nv_bfloat162*)(whi + OFF_WXZ), (__nv_bfloat162*)(wlo + OFF_WXZ));
    conv_kernel<<<1024, 256>>>((const float4*)Whz, (__nv_bfloat162*)(whi + OFF_WHZ), (__nv_bfloat162*)(wlo + OFF_WHZ));
    conv_kernel<<<1024, 256>>>((const float4*)Wxh, (__nv_bfloat162*)(whi + OFF_WXH), (__nv_bfloat162*)(wlo + OFF_WXH));
    conv_kernel<<<1024, 256>>>((const float4*)Whh, (__nv_bfloat162*)(whi + OFF_WHH), (__nv_bfloat162*)(wlo + OFF_WHH));
    conv_kernel<<<2048, 256>>>((const float4*)Wc,   (__nv_bfloat162*)(whi + OFF_WC),   (__nv_bfloat162*)(wlo + OFF_WC));
    conv_kernel<<<2048, 256>>>((const float4*)What, (__nv_bfloat162*)(whi + OFF_WHAT), (__nv_bfloat162*)(wlo + OFF_WHAT));

    // fused multi-output GEMM: r (->rh hi/lo), z, c, hat
    gemm_tc<0><<<dim3(32, 64), THREADS, SMEM_TOTAL>>>(br, bz, bh, bc, bhat, h, nullptr);

    // g_hat *= softmax(g_c)
    softmax_kernel<<<BATCH, 256>>>();

    // final: acc = rh@Whh^T + x@Wxh^T ; out = (1-z)*tanh(acc+bh) + z*h + hat
    gemm_tc<1><<<dim3(8, 64), THREADS, SMEM_TOTAL>>>(br, bz, bh, bc, bhat, h, out);
}

// round 5
// speedup vs baseline: 8.7538x; 2.4106x over previous
#include <cuda_runtime.h>
#include <cuda_fp16.h>
#include <cstdint>
#include <math.h>

#define BATCH 8192
#define HID   1024
#define M1    1048576

// ---------------- device scratch (no allocations allowed) ----------------
__device__ __half g_w16[10 * M1];
__device__ __half g_x16[BATCH * HID];
__device__ __half g_h16[BATCH * HID];
__device__ __half g_rh16[BATCH * HID];
__device__ float g_z[BATCH * HID];
__device__ float g_c[BATCH * HID];
__device__ float g_hat[BATCH * HID];

#define OFF_WXR  0
#define OFF_WHR  (1 * M1)
#define OFF_WXZ  (2 * M1)
#define OFF_WHZ  (3 * M1)
#define OFF_WXH  (4 * M1)
#define OFF_WHH  (5 * M1)
#define OFF_WC   (6 * M1)
#define OFF_WHAT (8 * M1)

// ---------------- helpers ----------------
__device__ __forceinline__ uint32_t smem_u32(const void* p) {
    uint32_t a;
    asm("{ .reg .u64 t; cvta.to.shared.u64 t, %1; cvt.u32.u64 %0, t; }" : "=r"(a) : "l"(p));
    return a;
}
__device__ __forceinline__ void cp16(uint32_t s, const void* g) {
    asm volatile("cp.async.cg.shared.global [%0], [%1], 16;" :: "r"(s), "l"(g));
}
__device__ __forceinline__ void ldsm4(uint32_t (&r)[4], uint32_t addr) {
    asm volatile("ldmatrix.sync.aligned.m8n8.x4.shared.b16 {%0,%1,%2,%3}, [%4];"
        : "=r"(r[0]), "=r"(r[1]), "=r"(r[2]), "=r"(r[3]) : "r"(addr));
}
__device__ __forceinline__ void mma_f16(float (&d)[4], const uint32_t (&a)[4],
                                        uint32_t b0, uint32_t b1) {
    asm volatile("mma.sync.aligned.m16n8k16.row.col.f32.f16.f16.f32 "
        "{%0,%1,%2,%3}, {%4,%5,%6,%7}, {%8,%9}, {%0,%1,%2,%3};"
        : "+f"(d[0]), "+f"(d[1]), "+f"(d[2]), "+f"(d[3])
        : "r"(a[0]), "r"(a[1]), "r"(a[2]), "r"(a[3]), "r"(b0), "r"(b1));
}

// ---------------- GEMM config ----------------
// Tile 128x128, K-chunk 64 (fp16 -> 128B rows, SW128 swizzle), 3-stage cp.async.
// 8 warps: 2 (M) x 4 (N); warp tile 64x32. 96 KB smem, 2 CTA/SM.
#define THREADS 256
#define STAGE_BYTES 16384          // one operand tile: 128 rows * 128B
#define SMEM_TOTAL (3 * 2 * STAGE_BYTES)

// load one 64-K chunk: A 128 rows (lda=1024), B 128 rows (ldb variable).
__device__ __forceinline__ void load_chunk(uint32_t sA, uint32_t sB,
    const __half* __restrict__ a, const __half* __restrict__ b,
    int ldb, int m0, int bn, int k0, int tid)
{
#pragma unroll
    for (int it = 0; it < 4; it++) {
        int s = tid + it * 256;
        int r = s >> 3, cc = s & 7;
        uint32_t off = r * 128 + ((cc * 16) ^ ((r & 7) << 4));
        cp16(sA + off, a + (size_t)(m0 + r) * 1024 + k0 + cc * 8);
    }
#pragma unroll
    for (int it = 0; it < 4; it++) {
        int s = tid + it * 256;
        int r = s >> 3, cc = s & 7;
        uint32_t off = r * 128 + ((cc * 16) ^ ((r & 7) << 4));
        cp16(sB + off, b + (size_t)(bn + r) * (size_t)ldb + k0 + cc * 8);
    }
    asm volatile("cp.async.commit_group;" ::: "memory");
}

// FINAL=0: virtual outputs o=0..3 (r,z,c,hat), grid (32, 64): o=bx>>3, bn=(bx&7)*128
// FINAL=1: pairs {rh@Whh^T, x@Wxh^T} accumulated -> fused output, grid (8, 64)
template <int FINAL>
__global__ __launch_bounds__(THREADS, 2)
void gemm_tc(const float* __restrict__ br, const float* __restrict__ bz,
             const float* __restrict__ bh, const float* __restrict__ bc,
             const float* __restrict__ bhat, const float* __restrict__ hprev,
             float* __restrict__ out)
{
    extern __shared__ char smem[];
    const uint32_t sb = smem_u32(smem);
    const int tid = threadIdx.x;
    const int lane = tid & 31;
    const int wid = tid >> 5;
    const int wm = wid >> 2;      // 0..1
    const int wn = wid & 3;       // 0..3
    const int m0 = blockIdx.y * 128;

    int o, bn;
    if (FINAL) { o = 4; bn = blockIdx.x * 128; }
    else       { o = blockIdx.x >> 3; bn = (blockIdx.x & 7) * 128; }

    const __half *aSrc[2] = {g_x16, g_h16};
    const __half *bSrc[2] = {0, 0};
    int ldbv = 1024;
    const float* bias = 0;
    switch (o) {
        case 0: bSrc[0] = g_w16 + OFF_WXR; bSrc[1] = g_w16 + OFF_WHR; bias = br; break;
        case 1: bSrc[0] = g_w16 + OFF_WXZ; bSrc[1] = g_w16 + OFF_WHZ; bias = bz; break;
        case 2: bSrc[0] = g_w16 + OFF_WC;  bSrc[1] = g_w16 + OFF_WC + 1024;
                ldbv = 2048; bias = bc; break;
        case 3: bSrc[0] = g_w16 + OFF_WHAT; bSrc[1] = g_w16 + OFF_WHAT + 1024;
                ldbv = 2048; bias = bhat; break;
        default: // FINAL: pair0 = rh@Whh, pair1 = x@Wxh
                 aSrc[0] = g_rh16; aSrc[1] = g_x16;
                 bSrc[0] = g_w16 + OFF_WHH; bSrc[1] = g_w16 + OFF_WXH;
                 bias = bh; break;
    }

    // per-thread ldmatrix offsets (within a stage tile)
    uint32_t aPre[4], axr[4];
#pragma unroll
    for (int mt = 0; mt < 4; mt++) {
        int r = wm * 64 + mt * 16 + (lane & 15);
        aPre[mt] = (uint32_t)(r * 128);
        axr[mt] = (uint32_t)((r & 7) << 4);
    }
    const uint32_t acx = (uint32_t)((lane >> 4) << 4);
    uint32_t bPre[2], bxr[2];
#pragma unroll
    for (int nt = 0; nt < 2; nt++) {
        int r = wn * 32 + nt * 16 + (lane & 7) + ((lane >> 4) << 3);
        bPre[nt] = (uint32_t)(r * 128);
        bxr[nt] = (uint32_t)((r & 7) << 4);
    }
    const uint32_t bcx = (uint32_t)(((lane >> 3) & 1) << 4);

    float acc[4][4][4];
#pragma unroll
    for (int i = 0; i < 4; i++)
#pragma unroll
        for (int j = 0; j < 4; j++)
#pragma unroll
            for (int k = 0; k < 4; k++) acc[i][j][k] = 0.0f;

    const int total = 32;   // 2 pairs x 16 K-chunks of 64

    // prologue
    load_chunk(sb + 0 * STAGE_BYTES * 2, sb + 0 * STAGE_BYTES * 2 + STAGE_BYTES,
               aSrc[0], bSrc[0], ldbv, m0, bn, 0, tid);
    load_chunk(sb + 1 * STAGE_BYTES * 2, sb + 1 * STAGE_BYTES * 2 + STAGE_BYTES,
               aSrc[0], bSrc[0], ldbv, m0, bn, 64, tid);

    for (int ch = 0; ch < total; ch++) {
        if (ch == total - 1) asm volatile("cp.async.wait_group 0;" ::: "memory");
        else                 asm volatile("cp.async.wait_group 1;" ::: "memory");
        __syncthreads();

        int nc = ch + 2;
        if (nc < total) {
            int p = nc >> 4;
            int st = nc % 3;
            load_chunk(sb + st * STAGE_BYTES * 2, sb + st * STAGE_BYTES * 2 + STAGE_BYTES,
                       aSrc[p], bSrc[p], ldbv, m0, bn, (nc & 15) * 64, tid);
        }

        const uint32_t sA = sb + (ch % 3) * STAGE_BYTES * 2;
        const uint32_t sB = sA + STAGE_BYTES;
#pragma unroll
        for (int ks = 0; ks < 4; ks++) {
            uint32_t A[4][4];
#pragma unroll
            for (int mt = 0; mt < 4; mt++)
                ldsm4(A[mt], sA + aPre[mt] + ((((uint32_t)ks << 5) | acx) ^ axr[mt]));
            uint32_t B[2][4];
#pragma unroll
            for (int nt = 0; nt < 2; nt++)
                ldsm4(B[nt], sB + bPre[nt] + ((((uint32_t)ks << 5) | bcx) ^ bxr[nt]));
#pragma unroll
            for (int mt = 0; mt < 4; mt++)
#pragma unroll
                for (int j = 0; j < 4; j++)
                    mma_f16(acc[mt][j], A[mt], B[j >> 1][(j & 1) * 2], B[j >> 1][(j & 1) * 2 + 1]);
        }
    }

    // ---------------- fused epilogue ----------------
#pragma unroll
    for (int mt = 0; mt < 4; mt++) {
#pragma unroll
        for (int j = 0; j < 4; j++) {
            const int c0 = bn + wn * 32 + j * 8 + (lane & 3) * 2;
#pragma unroll
            for (int half = 0; half < 2; half++) {
                const int row = m0 + wm * 64 + mt * 16 + (lane >> 2) + half * 8;
                const size_t idx = (size_t)row * HID + c0;
                float v0 = acc[mt][j][half * 2 + 0];
                float v1 = acc[mt][j][half * 2 + 1];
                if (FINAL) {
                    float t0 = tanhf(v0 + bias[c0]);
                    float t1 = tanhf(v1 + bias[c0 + 1]);
                    float z0 = g_z[idx], z1 = g_z[idx + 1];
                    out[idx]     = (1.0f - z0) * t0 + z0 * hprev[idx]     + g_hat[idx];
                    out[idx + 1] = (1.0f - z1) * t1 + z1 * hprev[idx + 1] + g_hat[idx + 1];
                } else if (o == 0) {
                    float s0 = 1.0f / (1.0f + expf(-(v0 + bias[c0])));
                    float s1 = 1.0f / (1.0f + expf(-(v1 + bias[c0 + 1])));
                    float rh0 = s0 * hprev[idx], rh1 = s1 * hprev[idx + 1];
                    *(__half2*)(g_rh16 + idx) = __floats2half2_rn(rh0, rh1);
                } else if (o == 1) {
                    g_z[idx]     = 1.0f / (1.0f + expf(-(v0 + bias[c0])));
                    g_z[idx + 1] = 1.0f / (1.0f + expf(-(v1 + bias[c0 + 1])));
                } else if (o == 2) {
                    g_c[idx]     = v0 + bias[c0];
                    g_c[idx + 1] = v1 + bias[c0 + 1];
                } else {
                    g_hat[idx]     = fmaxf(v0 + bias[c0], 0.0f);
                    g_hat[idx + 1] = fmaxf(v1 + bias[c0 + 1], 0.0f);
                }
            }
        }
    }
}

// ---------------- fp32 -> fp16 convert ----------------
__global__ __launch_bounds__(256)
void conv16(const float4* __restrict__ src, __half2* __restrict__ dst)
{
    int i = blockIdx.x * 256 + threadIdx.x;
    float4 f = src[i];
    dst[2 * i]     = __floats2half2_rn(f.x, f.y);
    dst[2 * i + 1] = __floats2half2_rn(f.z, f.w);
}

// ---------------- row softmax: g_hat *= softmax(g_c) ----------------
__global__ __launch_bounds__(256)
void softmax_kernel()
{
    const int row = blockIdx.x;
    const int tid = threadIdx.x;
    const size_t base = (size_t)row * HID;
    __shared__ float sh[8];

    float v[4];
    float mx = -1e30f;
#pragma unroll
    for (int i = 0; i < 4; i++) {
        v[i] = g_c[base + tid + i * 256];
        mx = fmaxf(mx, v[i]);
    }
#pragma unroll
    for (int off = 16; off > 0; off >>= 1) mx = fmaxf(mx, __shfl_xor_sync(0xffffffffu, mx, off));
    if ((tid & 31) == 0) sh[tid >> 5] = mx;
    __syncthreads();
    mx = sh[0];
#pragma unroll
    for (int i = 1; i < 8; i++) mx = fmaxf(mx, sh[i]);
    __syncthreads();

    float s = 0.0f;
#pragma unroll
    for (int i = 0; i < 4; i++) { v[i] = expf(v[i] - mx); s += v[i]; }
#pragma unroll
    for (int off = 16; off > 0; off >>= 1) s += __shfl_xor_sync(0xffffffffu, s, off);
    if ((tid & 31) == 0) sh[tid >> 5] = s;
    __syncthreads();
    s = 0.0f;
#pragma unroll
    for (int i = 0; i < 8; i++) s += sh[i];
    const float inv = 1.0f / s;

#pragma unroll
    for (int i = 0; i < 4; i++) {
        size_t idx = base + tid + i * 256;
        g_hat[idx] *= v[i] * inv;
    }
}

extern "C" void kernel_launch(void* const* d_in, const int* in_sizes, int n_in,
                              void* d_out, int out_size)
{
    (void)in_sizes; (void)n_in; (void)out_size;
    const float* x    = (const float*)d_in[0];
    const float* h    = (const float*)d_in[1];
    const float* Wxr  = (const float*)d_in[2];
    const float* Whr  = (const float*)d_in[3];
    const float* br   = (const float*)d_in[4];
    const float* Wxz  = (const float*)d_in[5];
    const float* Whz  = (const float*)d_in[6];
    const float* bz   = (const float*)d_in[7];
    const float* Wxh  = (const float*)d_in[8];
    const float* Whh  = (const float*)d_in[9];
    const float* bh   = (const float*)d_in[10];
    const float* Wc   = (const float*)d_in[11];
    const float* bc   = (const float*)d_in[12];
    const float* What = (const float*)d_in[13];
    const float* bhat = (const float*)d_in[14];
    float* out = (float*)d_out;

    __half *w16, *x16, *h16;
    cudaGetSymbolAddress((void**)&w16, g_w16);
    cudaGetSymbolAddress((void**)&x16, g_x16);
    cudaGetSymbolAddress((void**)&h16, g_h16);

    cudaFuncSetAttribute(gemm_tc<0>, cudaFuncAttributeMaxDynamicSharedMemorySize, SMEM_TOTAL);
    cudaFuncSetAttribute(gemm_tc<1>, cudaFuncAttributeMaxDynamicSharedMemorySize, SMEM_TOTAL);

    conv16<<<8192, 256>>>((const float4*)x, (__half2*)x16);
    conv16<<<8192, 256>>>((const float4*)h, (__half2*)h16);
    conv16<<<1024, 256>>>((const float4*)Wxr, (__half2*)(w16 + OFF_WXR));
    conv16<<<1024, 256>>>((const float4*)Whr, (__half2*)(w16 + OFF_WHR));
    conv16<<<1024, 256>>>((const float4*)Wxz, (__half2*)(w16 + OFF_WXZ));
    conv16<<<1024, 256>>>((const float4*)Whz, (__half2*)(w16 + OFF_WHZ));
    conv16<<<1024, 256>>>((const float4*)Wxh, (__half2*)(w16 + OFF_WXH));
    conv16<<<1024, 256>>>((const float4*)Whh, (__half2*)(w16 + OFF_WHH));
    conv16<<<2048, 256>>>((const float4*)Wc,   (__half2*)(w16 + OFF_WC));
    conv16<<<2048, 256>>>((const float4*)What, (__half2*)(w16 + OFF_WHAT));

    // fused multi-output GEMM: r (->rh fp16), z, c, hat
    gemm_tc<0><<<dim3(32, 64), THREADS, SMEM_TOTAL>>>(br, bz, bh, bc, bhat, h, nullptr);

    // g_hat *= softmax(g_c)
    softmax_kernel<<<BATCH, 256>>>();

    // final: acc = rh@Whh^T + x@Wxh^T ; out = (1-z)*tanh(acc+bh) + z*h + hat
    gemm_tc<1><<<dim3(8, 64), THREADS, SMEM_TOTAL>>>(br, bz, bh, bc, bhat, h, out);
}

// round 6
// speedup vs baseline: 9.2217x; 1.0534x over previous
#include <cuda_runtime.h>
#include <cuda_fp16.h>
#include <cstdint>
#include <math.h>

#define BATCH 8192
#define HID   1024
#define M1    1048576

// ---------------- device scratch (no allocations allowed) ----------------
__device__ __half g_w16[10 * M1];
__device__ __half g_x16[BATCH * HID];
__device__ __half g_h16[BATCH * HID];
__device__ __half g_rh16[BATCH * HID];
__device__ float  g_z[BATCH * HID];
__device__ __half g_c16[BATCH * HID];
__device__ __half g_hat16[BATCH * HID];

#define OFF_WXR  0
#define OFF_WHR  (1 * M1)
#define OFF_WXZ  (2 * M1)
#define OFF_WHZ  (3 * M1)
#define OFF_WXH  (4 * M1)
#define OFF_WHH  (5 * M1)
#define OFF_WC   (6 * M1)
#define OFF_WHAT (8 * M1)

// ---------------- helpers ----------------
__device__ __forceinline__ uint32_t smem_u32(const void* p) {
    uint32_t a;
    asm("{ .reg .u64 t; cvta.to.shared.u64 t, %1; cvt.u32.u64 %0, t; }" : "=r"(a) : "l"(p));
    return a;
}
__device__ __forceinline__ void cp16(uint32_t s, const void* g) {
    asm volatile("cp.async.cg.shared.global [%0], [%1], 16;" :: "r"(s), "l"(g));
}
__device__ __forceinline__ void ldsm4(uint32_t (&r)[4], uint32_t addr) {
    asm volatile("ldmatrix.sync.aligned.m8n8.x4.shared.b16 {%0,%1,%2,%3}, [%4];"
        : "=r"(r[0]), "=r"(r[1]), "=r"(r[2]), "=r"(r[3]) : "r"(addr));
}
__device__ __forceinline__ void mma_f16(float (&d)[4], const uint32_t (&a)[4],
                                        uint32_t b0, uint32_t b1) {
    asm volatile("mma.sync.aligned.m16n8k16.row.col.f32.f16.f16.f32 "
        "{%0,%1,%2,%3}, {%4,%5,%6,%7}, {%8,%9}, {%0,%1,%2,%3};"
        : "+f"(d[0]), "+f"(d[1]), "+f"(d[2]), "+f"(d[3])
        : "r"(a[0]), "r"(a[1]), "r"(a[2]), "r"(a[3]), "r"(b0), "r"(b1));
}

// ---------------- GEMM config ----------------
#define THREADS 256
#define STAGE_BYTES 16384
#define SMEM_TOTAL (3 * 2 * STAGE_BYTES)

__device__ __forceinline__ void load_chunk(uint32_t sA, uint32_t sB,
    const __half* __restrict__ a, const __half* __restrict__ b,
    int ldb, int m0, int bn, int k0, int tid)
{
#pragma unroll
    for (int it = 0; it < 4; it++) {
        int s = tid + it * 256;
        int r = s >> 3, cc = s & 7;
        uint32_t off = r * 128 + ((cc * 16) ^ ((r & 7) << 4));
        cp16(sA + off, a + (size_t)(m0 + r) * 1024 + k0 + cc * 8);
    }
#pragma unroll
    for (int it = 0; it < 4; it++) {
        int s = tid + it * 256;
        int r = s >> 3, cc = s & 7;
        uint32_t off = r * 128 + ((cc * 16) ^ ((r & 7) << 4));
        cp16(sB + off, b + (size_t)(bn + r) * (size_t)ldb + k0 + cc * 8);
    }
    asm volatile("cp.async.commit_group;" ::: "memory");
}

// FINAL=0: o=0..3 (r,z,c,hat), grid (32, 64): o=bx>>3, bn=(bx&7)*128
// FINAL=1: pairs {rh@Whh^T, x@Wxh^T} accumulated -> fused output, grid (8, 64)
template <int FINAL>
__global__ __launch_bounds__(THREADS, 2)
void gemm_tc(const float* __restrict__ br, const float* __restrict__ bz,
             const float* __restrict__ bh, const float* __restrict__ bc,
             const float* __restrict__ bhat, const float* __restrict__ hprev,
             float* __restrict__ out)
{
    extern __shared__ char smem[];
    const uint32_t sb = smem_u32(smem);
    const int tid = threadIdx.x;
    const int lane = tid & 31;
    const int wid = tid >> 5;
    const int wm = wid >> 2;
    const int wn = wid & 3;
    const int m0 = blockIdx.y * 128;

    int o, bn;
    if (FINAL) { o = 4; bn = blockIdx.x * 128; }
    else       { o = blockIdx.x >> 3; bn = (blockIdx.x & 7) * 128; }

    const __half *aSrc[2] = {g_x16, g_h16};
    const __half *bSrc[2] = {0, 0};
    int ldbv = 1024;
    const float* bias = 0;
    switch (o) {
        case 0: bSrc[0] = g_w16 + OFF_WXR; bSrc[1] = g_w16 + OFF_WHR; bias = br; break;
        case 1: bSrc[0] = g_w16 + OFF_WXZ; bSrc[1] = g_w16 + OFF_WHZ; bias = bz; break;
        case 2: bSrc[0] = g_w16 + OFF_WC;  bSrc[1] = g_w16 + OFF_WC + 1024;
                ldbv = 2048; bias = bc; break;
        case 3: bSrc[0] = g_w16 + OFF_WHAT; bSrc[1] = g_w16 + OFF_WHAT + 1024;
                ldbv = 2048; bias = bhat; break;
        default: aSrc[0] = g_rh16; aSrc[1] = g_x16;
                 bSrc[0] = g_w16 + OFF_WHH; bSrc[1] = g_w16 + OFF_WXH;
                 bias = bh; break;
    }

    // packed ldmatrix address components: base-row bits (>=7) | xor bits (4..6)
    uint32_t aC[4];
#pragma unroll
    for (int mt = 0; mt < 4; mt++) {
        int r = wm * 64 + mt * 16 + (lane & 15);
        aC[mt] = (uint32_t)(r * 128) | (uint32_t)((r & 7) << 4);
    }
    const uint32_t acx = (uint32_t)((lane >> 4) << 4);
    uint32_t bC[2];
#pragma unroll
    for (int nt = 0; nt < 2; nt++) {
        int r = wn * 32 + nt * 16 + (lane & 7) + ((lane >> 4) << 3);
        bC[nt] = (uint32_t)(r * 128) | (uint32_t)((r & 7) << 4);
    }
    const uint32_t bcx = (uint32_t)(((lane >> 3) & 1) << 4);

    float acc[4][4][4];
#pragma unroll
    for (int i = 0; i < 4; i++)
#pragma unroll
        for (int j = 0; j < 4; j++)
#pragma unroll
            for (int k = 0; k < 4; k++) acc[i][j][k] = 0.0f;

    const int total = 32;   // 2 pairs x 16 K-chunks of 64

    load_chunk(sb + 0 * STAGE_BYTES * 2, sb + 0 * STAGE_BYTES * 2 + STAGE_BYTES,
               aSrc[0], bSrc[0], ldbv, m0, bn, 0, tid);
    load_chunk(sb + 1 * STAGE_BYTES * 2, sb + 1 * STAGE_BYTES * 2 + STAGE_BYTES,
               aSrc[0], bSrc[0], ldbv, m0, bn, 64, tid);

    for (int ch = 0; ch < total; ch++) {
        if (ch == total - 1) asm volatile("cp.async.wait_group 0;" ::: "memory");
        else                 asm volatile("cp.async.wait_group 1;" ::: "memory");
        __syncthreads();

        int nc = ch + 2;
        if (nc < total) {
            int p = nc >> 4;
            int st = nc % 3;
            load_chunk(sb + st * STAGE_BYTES * 2, sb + st * STAGE_BYTES * 2 + STAGE_BYTES,
                       aSrc[p], bSrc[p], ldbv, m0, bn, (nc & 15) * 64, tid);
        }

        const uint32_t sA = sb + (ch % 3) * STAGE_BYTES * 2;
        const uint32_t sB = sA + STAGE_BYTES;

        // register double-buffered fragment pipeline over ks = 0..3
        uint32_t Af[2][4][4], Bf[2][2][4];
#pragma unroll
        for (int mt = 0; mt < 4; mt++) ldsm4(Af[0][mt], sA + (aC[mt] ^ acx));
#pragma unroll
        for (int nt = 0; nt < 2; nt++) ldsm4(Bf[0][nt], sB + (bC[nt] ^ bcx));
#pragma unroll
        for (int ks = 0; ks < 4; ks++) {
            const int cur = ks & 1, nxt = cur ^ 1;
            if (ks < 3) {
                const uint32_t qa = ((uint32_t)(ks + 1) << 5) | acx;
                const uint32_t qb = ((uint32_t)(ks + 1) << 5) | bcx;
#pragma unroll
                for (int mt = 0; mt < 4; mt++) ldsm4(Af[nxt][mt], sA + (aC[mt] ^ qa));
#pragma unroll
                for (int nt = 0; nt < 2; nt++) ldsm4(Bf[nxt][nt], sB + (bC[nt] ^ qb));
            }
#pragma unroll
            for (int mt = 0; mt < 4; mt++)
#pragma unroll
                for (int j = 0; j < 4; j++)
                    mma_f16(acc[mt][j], Af[cur][mt],
                            Bf[cur][j >> 1][(j & 1) * 2], Bf[cur][j >> 1][(j & 1) * 2 + 1]);
        }
    }

    // ---------------- fused epilogue ----------------
#pragma unroll
    for (int mt = 0; mt < 4; mt++) {
#pragma unroll
        for (int j = 0; j < 4; j++) {
            const int c0 = bn + wn * 32 + j * 8 + (lane & 3) * 2;
#pragma unroll
            for (int half = 0; half < 2; half++) {
                const int row = m0 + wm * 64 + mt * 16 + (lane >> 2) + half * 8;
                const size_t idx = (size_t)row * HID + c0;
                float v0 = acc[mt][j][half * 2 + 0];
                float v1 = acc[mt][j][half * 2 + 1];
                if (FINAL) {
                    float t0 = tanhf(v0 + bias[c0]);
                    float t1 = tanhf(v1 + bias[c0 + 1]);
                    float z0 = g_z[idx], z1 = g_z[idx + 1];
                    float2 hh = __half22float2(*(const __half2*)(g_hat16 + idx));
                    out[idx]     = (1.0f - z0) * t0 + z0 * hprev[idx]     + hh.x;
                    out[idx + 1] = (1.0f - z1) * t1 + z1 * hprev[idx + 1] + hh.y;
                } else if (o == 0) {
                    float s0 = 1.0f / (1.0f + expf(-(v0 + bias[c0])));
                    float s1 = 1.0f / (1.0f + expf(-(v1 + bias[c0 + 1])));
                    float rh0 = s0 * hprev[idx], rh1 = s1 * hprev[idx + 1];
                    *(__half2*)(g_rh16 + idx) = __floats2half2_rn(rh0, rh1);
                } else if (o == 1) {
                    g_z[idx]     = 1.0f / (1.0f + expf(-(v0 + bias[c0])));
                    g_z[idx + 1] = 1.0f / (1.0f + expf(-(v1 + bias[c0 + 1])));
                } else if (o == 2) {
                    *(__half2*)(g_c16 + idx) = __floats2half2_rn(v0 + bias[c0], v1 + bias[c0 + 1]);
                } else {
                    *(__half2*)(g_hat16 + idx) =
                        __floats2half2_rn(fmaxf(v0 + bias[c0], 0.0f), fmaxf(v1 + bias[c0 + 1], 0.0f));
                }
            }
        }
    }
}

// ---------------- batched fp32 -> fp16 convert (one launch) ----------------
struct ConvJob {
    const float4* src[10];
    __half2* dst[10];
    int end4[10];   // cumulative float4 counts
};

#define CONV_TOTAL4 6815744   // 2*2097152 + 6*262144 + 2*524288

__global__ __launch_bounds__(256)
void convall(ConvJob j)
{
    const int gid = blockIdx.x * 256 + threadIdx.x;
#pragma unroll
    for (int rep = 0; rep < 2; rep++) {
        int i = gid + rep * (CONV_TOTAL4 / 2);
        int s = 0;
#pragma unroll
        for (int t = 0; t < 9; t++) s += (i >= j.end4[t]) ? 1 : 0;
        int base = (s == 0) ? 0 : j.end4[s - 1];
        int k = i - base;
        float4 f = j.src[s][k];
        j.dst[s][2 * k]     = __floats2half2_rn(f.x, f.y);
        j.dst[s][2 * k + 1] = __floats2half2_rn(f.z, f.w);
    }
}

// ---------------- row softmax: g_hat16 *= softmax(g_c16) ----------------
__global__ __launch_bounds__(256)
void softmax_kernel()
{
    const int row = blockIdx.x;
    const int tid = threadIdx.x;
    const size_t base2 = (size_t)row * 512;   // half2 units
    const __half2* c2 = (const __half2*)g_c16;
    __half2* t2 = (__half2*)g_hat16;
    __shared__ float sh[8];

    float2 v[2];
    float mx = -1e30f;
#pragma unroll
    for (int i = 0; i < 2; i++) {
        v[i] = __half22float2(c2[base2 + tid + i * 256]);
        mx = fmaxf(mx, fmaxf(v[i].x, v[i].y));
    }
#pragma unroll
    for (int off = 16; off > 0; off >>= 1) mx = fmaxf(mx, __shfl_xor_sync(0xffffffffu, mx, off));
    if ((tid & 31) == 0) sh[tid >> 5] = mx;
    __syncthreads();
    mx = sh[0];
#pragma unroll
    for (int i = 1; i < 8; i++) mx = fmaxf(mx, sh[i]);
    __syncthreads();

    float s = 0.0f;
#pragma unroll
    for (int i = 0; i < 2; i++) {
        v[i].x = expf(v[i].x - mx);
        v[i].y = expf(v[i].y - mx);
        s += v[i].x + v[i].y;
    }
#pragma unroll
    for (int off = 16; off > 0; off >>= 1) s += __shfl_xor_sync(0xffffffffu, s, off);
    if ((tid & 31) == 0) sh[tid >> 5] = s;
    __syncthreads();
    s = 0.0f;
#pragma unroll
    for (int i = 0; i < 8; i++) s += sh[i];
    const float inv = 1.0f / s;

#pragma unroll
    for (int i = 0; i < 2; i++) {
        size_t idx = base2 + tid + i * 256;
        float2 hh = __half22float2(t2[idx]);
        t2[idx] = __floats2half2_rn(hh.x * v[i].x * inv, hh.y * v[i].y * inv);
    }
}

extern "C" void kernel_launch(void* const* d_in, const int* in_sizes, int n_in,
                              void* d_out, int out_size)
{
    (void)in_sizes; (void)n_in; (void)out_size;
    const float* x    = (const float*)d_in[0];
    const float* h    = (const float*)d_in[1];
    const float* Wxr  = (const float*)d_in[2];
    const float* Whr  = (const float*)d_in[3];
    const float* br   = (const float*)d_in[4];
    const float* Wxz  = (const float*)d_in[5];
    const float* Whz  = (const float*)d_in[6];
    const float* bz   = (const float*)d_in[7];
    const float* Wxh  = (const float*)d_in[8];
    const float* Whh  = (const float*)d_in[9];
    const float* bh   = (const float*)d_in[10];
    const float* Wc   = (const float*)d_in[11];
    const float* bc   = (const float*)d_in[12];
    const float* What = (const float*)d_in[13];
    const float* bhat = (const float*)d_in[14];
    float* out = (float*)d_out;

    __half *w16, *x16, *h16;
    cudaGetSymbolAddress((void**)&w16, g_w16);
    cudaGetSymbolAddress((void**)&x16, g_x16);
    cudaGetSymbolAddress((void**)&h16, g_h16);

    cudaFuncSetAttribute(gemm_tc<0>, cudaFuncAttributeMaxDynamicSharedMemorySize, SMEM_TOTAL);
    cudaFuncSetAttribute(gemm_tc<1>, cudaFuncAttributeMaxDynamicSharedMemorySize, SMEM_TOTAL);

    ConvJob j;
    const float* srcs[10] = {x, h, Wxr, Whr, Wxz, Whz, Wxh, Whh, Wc, What};
    __half* dsts[10] = {x16, h16, w16 + OFF_WXR, w16 + OFF_WHR, w16 + OFF_WXZ,
                        w16 + OFF_WHZ, w16 + OFF_WXH, w16 + OFF_WHH,
                        w16 + OFF_WC, w16 + OFF_WHAT};
    const int cnt4[10] = {2097152, 2097152, 262144, 262144, 262144, 262144,
                          262144, 262144, 524288, 524288};
    int acc4 = 0;
    for (int i = 0; i < 10; i++) {
        j.src[i] = (const float4*)srcs[i];
        j.dst[i] = (__half2*)dsts[i];
        acc4 += cnt4[i];
        j.end4[i] = acc4;
    }

    convall<<<CONV_TOTAL4 / 2 / 256, 256>>>(j);

    // fused multi-output GEMM: r (->rh fp16), z, c16, hat16
    gemm_tc<0><<<dim3(32, 64), THREADS, SMEM_TOTAL>>>(br, bz, bh, bc, bhat, h, nullptr);

    // g_hat16 *= softmax(g_c16)
    softmax_kernel<<<BATCH, 256>>>();

    // final: acc = rh@Whh^T + x@Wxh^T ; out = (1-z)*tanh(acc+bh) + z*h + hat
    gemm_tc<1><<<dim3(8, 64), THREADS, SMEM_TOTAL>>>(br, bz, bh, bc, bhat, h, out);
}